// round 17
// baseline (speedup 1.0000x reference)
#include <cuda_runtime.h>
#include <cuda_bf16.h>
#include <mma.h>
#include <cstdint>
using namespace nvcuda;

#define T_ 8
#define N_ 1024
#define D_ 128
#define JC_ 4                    // j-chunks (split of the attention j loop)
static constexpr float SCALE = 0.08838834764831845f; // 1/sqrt(128)

// ---- scratch (__device__ globals; no allocation allowed) ----
__device__ __align__(16) __nv_bfloat16 g_Xh[T_ * N_ * D_];            // 2 MB
__device__ __align__(16) unsigned      g_adjp[N_ * (N_ / 32)];        // 128 KB bitmask
__device__ __align__(16) float         g_Opart[JC_ * T_ * N_ * D_];   // 16 MB partial numerators (fp32)
__device__ __align__(16) float         g_lpart[JC_ * T_ * N_];        // 128 KB partial denominators

// ---------------- PTX helpers ----------------
__device__ __forceinline__ uint32_t smaddr(const void* p) {
    return (uint32_t)__cvta_generic_to_shared(p);
}
__device__ __forceinline__ void cpa16(uint32_t dst, const void* src) {
    asm volatile("cp.async.cg.shared.global [%0], [%1], 16;" :: "r"(dst), "l"(src));
}
__device__ __forceinline__ void cpa_commit() { asm volatile("cp.async.commit_group;"); }
template <int NN> __device__ __forceinline__ void cpa_wait() {
    asm volatile("cp.async.wait_group %0;" :: "n"(NN));
}
__device__ __forceinline__ void ldsm4(uint32_t& r0, uint32_t& r1, uint32_t& r2, uint32_t& r3,
                                      uint32_t a) {
    asm volatile("ldmatrix.sync.aligned.m8n8.x4.shared.b16 {%0,%1,%2,%3},[%4];"
                 : "=r"(r0), "=r"(r1), "=r"(r2), "=r"(r3) : "r"(a));
}
__device__ __forceinline__ void mma16816(float* c, uint32_t a0, uint32_t a1, uint32_t a2,
                                         uint32_t a3, uint32_t b0, uint32_t b1) {
    asm volatile("mma.sync.aligned.m16n8k16.row.col.f32.bf16.bf16.f32 "
                 "{%0,%1,%2,%3}, {%4,%5,%6,%7}, {%8,%9}, {%0,%1,%2,%3};"
                 : "+f"(c[0]), "+f"(c[1]), "+f"(c[2]), "+f"(c[3])
                 : "r"(a0), "r"(a1), "r"(a2), "r"(a3), "r"(b0), "r"(b1));
}

// ---------------- K0: fp32 -> bf16 cast ----------------
__global__ void k_cast(const float* __restrict__ x) {
    int i = blockIdx.x * blockDim.x + threadIdx.x;
    if (i < T_ * N_ * D_) g_Xh[i] = __float2bfloat16(x[i]);
}

// ---------------- K0b: pack adj into bitmask ----------------
__global__ void k_pack(const int* __restrict__ adj) {
    int idx = blockIdx.x * blockDim.x + threadIdx.x;   // over N*N
    unsigned m = __ballot_sync(~0u, adj[idx] > 0);
    if ((threadIdx.x & 31) == 0) g_adjp[idx >> 5] = m;
}

// ---------------- K1: fused partial attention (R16 proven; fp32 epilogue) ----------------
// grid (16, JC_, T_) = 512 blocks, 128 threads, smem 46 KB -> 4 blocks/SM
// -> one full wave. QK in registers (mma.m16n8k16), exp in registers,
// P->smem, wmma AV with persistent accumulators.
#define SM_XJ   17408
#define SM_P    34816
#define SM_ADJ  44032
#define SM_TOT  46080

__global__ void __launch_bounds__(128, 4) k_attn() {
    extern __shared__ char smraw[];
    __nv_bfloat16* Xms  = (__nv_bfloat16*)smraw;
    __nv_bfloat16* Xjp  = (__nv_bfloat16*)(smraw + SM_XJ);
    __nv_bfloat16* Pts  = (__nv_bfloat16*)(smraw + SM_P);
    unsigned*      adjs = (unsigned*)(smraw + SM_ADJ);
    float*         Osm  = (float*)smraw;    // epilogue only
    uint32_t smXm = smaddr(smraw);
    uint32_t smXj = smXm + SM_XJ;

    int m0 = blockIdx.x * 64;
    int jc = blockIdx.y;
    int t  = blockIdx.z;
    int jbase = jc * (N_ / JC_);            // 256-wide chunk
    int tid = threadIdx.x;
    int w    = tid >> 5;
    int lane = tid & 31;
    const __nv_bfloat16* Xt = g_Xh + (size_t)t * N_ * D_;

    // ---- load Xm tile (plain) + adj bits ----
    #pragma unroll
    for (int q = 0; q < 8; q++) {
        int idx = tid + q * 128;            // 1024 uint4
        int r = idx >> 4, c = (idx & 15) * 8;
        *(uint4*)&Xms[r * 136 + c] = *(const uint4*)&Xt[(m0 + r) * D_ + c];
    }
    #pragma unroll
    for (int q = 0; q < 4; q++) {
        int i = tid + q * 128;              // 512 words
        adjs[i] = g_adjp[(m0 + (i >> 3)) * 32 + jc * 8 + (i & 7)];
    }

    // ---- per-thread fragment constants ----
    int gr = lane >> 2, tc = lane & 3;      // C-frag: rows gr/gr+8, cols 2tc/2tc+1
    int lrow  = lane & 15;
    int lcol8 = 8 * (lane >> 4);
    uint32_t aoffA    = (uint32_t)((16 * w + lrow) * 136 + lcol8) * 2;
    uint32_t aoffBrow = (uint32_t)(lrow * 136 + lcol8) * 2;

    wmma::fragment<wmma::accumulator, 16, 16, 16, float> oacc[4][2];
    #pragma unroll
    for (int a = 0; a < 4; a++)
        #pragma unroll
        for (int b = 0; b < 2; b++) wmma::fill_fragment(oacc[a][b], 0.0f);

    float rs0 = 0.f, rs1 = 0.f;
    const int NIT = (N_ / JC_) / 64;        // 4 j-tiles per chunk

    #pragma unroll 1
    for (int it = 0; it < NIT; it++) {
        __syncthreads();                    // prev AV done -> Xj & P reusable
        int j0 = jbase + it * 64;
        #pragma unroll
        for (int q = 0; q < 8; q++) {       // FULL 1024 uint4 = 64x128 tile
            int idx = tid + q * 128;
            int r = idx >> 4, c = (idx & 15) * 8;
            cpa16(smXj + (uint32_t)(r * 136 + c) * 2, &Xt[(j0 + r) * D_ + c]);
        }
        cpa_commit();
        cpa_wait<0>();
        __syncthreads();                    // Xj visible to all warps

        // ---- QK: S(16x64) in registers ----
        float s[8][4];
        #pragma unroll
        for (int nb = 0; nb < 8; nb++)
            #pragma unroll
            for (int k = 0; k < 4; k++) s[nb][k] = 0.0f;

        #pragma unroll
        for (int ks = 0; ks < 8; ks++) {
            int k0 = ks * 16;
            uint32_t a0, a1, a2, a3;
            ldsm4(a0, a1, a2, a3, smXm + aoffA + (uint32_t)k0 * 2);
            #pragma unroll
            for (int p = 0; p < 4; p++) {
                uint32_t q0, q1, q2, q3;
                ldsm4(q0, q1, q2, q3, smXj + aoffBrow + (uint32_t)(16 * p * 136 + k0) * 2);
                mma16816(s[2 * p],     a0, a1, a2, a3, q0, q2);
                mma16816(s[2 * p + 1], a0, a1, a2, a3, q1, q3);
            }
        }

        // ---- mask + exp + rowsum; P -> smem ----
        {
            int rowE = 16 * w + gr;
            int ar0 = rowE * 8 + it * 2;
            int ar1 = (rowE + 8) * 8 + it * 2;
            unsigned w0a = adjs[ar0], w0b = adjs[ar0 + 1];
            unsigned w1a = adjs[ar1], w1b = adjs[ar1 + 1];
            #pragma unroll
            for (int nb = 0; nb < 8; nb++) {
                int col = 8 * nb + 2 * tc;
                unsigned wa = (nb < 4) ? w0a : w0b;
                unsigned wb = (nb < 4) ? w1a : w1b;
                int sh = col & 31;
                float e0 = ((wa >> sh) & 1u)       ? __expf(fminf(s[nb][0] * SCALE, 30.f)) : 0.f;
                float e1 = ((wa >> (sh + 1)) & 1u) ? __expf(fminf(s[nb][1] * SCALE, 30.f)) : 0.f;
                float f0 = ((wb >> sh) & 1u)       ? __expf(fminf(s[nb][2] * SCALE, 30.f)) : 0.f;
                float f1 = ((wb >> (sh + 1)) & 1u) ? __expf(fminf(s[nb][3] * SCALE, 30.f)) : 0.f;
                rs0 += e0 + e1;
                rs1 += f0 + f1;
                *(__nv_bfloat162*)&Pts[rowE * 72 + col]       = __floats2bfloat162_rn(e0, e1);
                *(__nv_bfloat162*)&Pts[(rowE + 8) * 72 + col] = __floats2bfloat162_rn(f0, f1);
            }
        }
        __syncthreads();                    // P complete for all 64 rows

        // ---- AV: O[:, 32w:+32] += P . Xj ----
        #pragma unroll
        for (int kk = 0; kk < 4; kk++) {
            wmma::fragment<wmma::matrix_b, 16, 16, 16, __nv_bfloat16, wmma::row_major> b0, b1;
            wmma::load_matrix_sync(b0, &Xjp[(kk * 16) * 136 + 32 * w], 136);
            wmma::load_matrix_sync(b1, &Xjp[(kk * 16) * 136 + 32 * w + 16], 136);
            #pragma unroll
            for (int rr = 0; rr < 4; rr++) {
                wmma::fragment<wmma::matrix_a, 16, 16, 16, __nv_bfloat16, wmma::row_major> af;
                wmma::load_matrix_sync(af, &Pts[(16 * rr) * 72 + kk * 16], 72);
                wmma::mma_sync(oacc[rr][0], af, b0, oacc[rr][0]);
                wmma::mma_sync(oacc[rr][1], af, b1, oacc[rr][1]);
            }
        }
    }

    // ---- epilogue: row sums + fp32 partial O ----
    __syncthreads();                        // AV done; Xm region reusable as Osm
    rs0 += __shfl_xor_sync(~0u, rs0, 1); rs0 += __shfl_xor_sync(~0u, rs0, 2);
    rs1 += __shfl_xor_sync(~0u, rs1, 1); rs1 += __shfl_xor_sync(~0u, rs1, 2);
    if (tc == 0) {
        int lbase = (jc * T_ + t) * N_ + m0;
        g_lpart[lbase + 16 * w + gr]     = rs0;
        g_lpart[lbase + 16 * w + gr + 8] = rs1;
    }
    #pragma unroll
    for (int rr = 0; rr < 4; rr++)
        #pragma unroll
        for (int cc = 0; cc < 2; cc++)
            wmma::store_matrix_sync(&Osm[(16 * rr) * 132 + 32 * w + 16 * cc],
                                    oacc[rr][cc], 132, wmma::mem_row_major);
    __syncthreads();
    float* Oout = g_Opart + ((size_t)(jc * T_ + t) * N_ + m0) * D_;
    #pragma unroll
    for (int q = 0; q < 16; q++) {
        int f4 = tid + q * 128;             // 2048 float4
        int r = f4 >> 5, c4 = (f4 & 31) * 4;
        const float* src = &Osm[r * 132 + c4];
        *(float4*)&Oout[r * D_ + c4] = make_float4(src[0], src[1], src[2], src[3]);
    }
}

// ---------------- K2: fused Gram-column + sigmoid + streaming expand ----------------
// 8192 blocks x 256 threads (8 warps = T_). Block r = s*N + j:
//   warp t reduces the JC_ chunks of rows t and s of node j in registers,
//   computes dot(Y_t, Y_s) via shuffle, l_t from g_lpart -> sigmoid weight
//   swv[t]; then all threads stream the contiguous 32KB output row.
// Tiny prefix (8 float4 loads/lane, mostly L2 after wave 1) overlaps other
// blocks' stores; DRAM store stream stays the binding resource.
__global__ void __launch_bounds__(256) k_expand(float* __restrict__ out) {
    __shared__ float linv_sm[T_];
    __shared__ float swv_sm[T_];
    int r = blockIdx.x;                     // 0..8191
    int s = r >> 10, j = r & 1023;
    int tid = threadIdx.x;
    int w = tid >> 5, lane = tid & 31;      // warp w == Gram row t=w

    // reduce rows w and s over JC_ chunks; lane covers d = 4*lane..+3
    const size_t strideC = (size_t)T_ * N_ * D_;
    const float* baseW = g_Opart + ((size_t)w * N_ + j) * D_ + lane * 4;
    const float* baseS = g_Opart + ((size_t)s * N_ + j) * D_ + lane * 4;
    float4 yw = make_float4(0.f, 0.f, 0.f, 0.f);
    float4 ys = make_float4(0.f, 0.f, 0.f, 0.f);
    #pragma unroll
    for (int c = 0; c < JC_; c++) {
        float4 a = *(const float4*)(baseW + c * strideC);
        yw.x += a.x; yw.y += a.y; yw.z += a.z; yw.w += a.w;
        float4 b = *(const float4*)(baseS + c * strideC);
        ys.x += b.x; ys.y += b.y; ys.z += b.z; ys.w += b.w;
    }
    float dot = yw.x * ys.x + yw.y * ys.y + yw.z * ys.z + yw.w * ys.w;
    #pragma unroll
    for (int o = 16; o; o >>= 1) dot += __shfl_xor_sync(~0u, dot, o);

    // l_w: lanes 0..3 hold the JC_ chunk partials; quad-reduce
    float lp = (lane < JC_) ? g_lpart[lane * T_ * N_ + w * N_ + j] : 0.f;
    lp += __shfl_xor_sync(~0u, lp, 1);
    lp += __shfl_xor_sync(~0u, lp, 2);
    if (lane == 0) linv_sm[w] = (lp > 0.f) ? (1.0f / lp) : 0.0f;  // inert guard
    __syncthreads();
    if (lane == 0) {
        float x = dot * linv_sm[w] * linv_sm[s] * SCALE;
        swv_sm[w] = 1.0f / (1.0f + __expf(-x));
    }
    __syncthreads();

    // stream the contiguous 32KB output row; t-segments consecutive
    float4* p = (float4*)out + (size_t)r * 2048 + tid;
    #pragma unroll
    for (int t = 0; t < T_; t++) {
        float v = swv_sm[t];
        __stcs(p, make_float4(v, v, v, v));
        p += 256;
    }
}

extern "C" void kernel_launch(void* const* d_in, const int* in_sizes, int n_in,
                              void* d_out, int out_size) {
    const float* raw = (const float*)d_in[0];
    const int*   adj = (const int*)d_in[1];
    float*       out = (float*)d_out;

    k_cast<<<(T_ * N_ * D_ + 255) / 256, 256>>>(raw);
    k_pack<<<(N_ * N_) / 256, 256>>>(adj);
    k_attn<<<dim3(16, JC_, T_), 128, SM_TOT>>>();
    k_expand<<<T_ * N_, 256>>>(out);
}